// round 1
// baseline (speedup 1.0000x reference)
#include <cuda_runtime.h>
#include <cuda_bf16.h>

#define FULLMASK 0xffffffffu

namespace {
constexpr int B = 64;
constexpr int T = 32768;
constexpr int R = 16;
}

__device__ __forceinline__ float lrelu(float v) { return v >= 0.f ? v : 0.1f * v; }
__device__ __forceinline__ float sigm(float v) {
    // 1/(1+e^-v) via ex2.approx (≈1 ulp) + rcp.approx — accurate enough for 1e-3.
    return __fdividef(1.f, 1.f + __expf(-v));
}
__device__ __forceinline__ float tanh_acc(float v) {
    // tanh via exp: 1 - 2/(e^{2v}+1). Saturates correctly for |v| large.
    float e = __expf(2.f * v);
    return 1.f - __fdividef(2.f, e + 1.f);
}

__global__ void __launch_bounds__(32, 1) hypergru_kernel(
    const float* __restrict__ x,      // [B,1,T]
    const float* __restrict__ c,      // [B,8]
    const float* __restrict__ h0,     // [1,B,R]
    const float* __restrict__ mlp_w1, // [8,8]
    const float* __restrict__ mlp_b1, // [8]
    const float* __restrict__ mlp_w2, // [8,8]
    const float* __restrict__ mlp_b2, // [8]
    const float* __restrict__ pih_w,  // [48,8]
    const float* __restrict__ pih_b,  // [48]
    const float* __restrict__ phh_w,  // [768,8]
    const float* __restrict__ phh_b,  // [768]
    const float* __restrict__ pbih_w, // [48,8]
    const float* __restrict__ pbih_b, // [48]
    const float* __restrict__ pbhh_w, // [48,8]
    const float* __restrict__ pbhh_b, // [48]
    const float* __restrict__ out_w,  // [1,16]
    const float* __restrict__ out_b,  // [1]
    float* __restrict__ out)          // y [B*T] then h_last [B*16]
{
    const int b    = blockIdx.x;
    const int lane = threadIdx.x;
    const int j    = lane & 15;   // hidden unit owned by this lane (replicated in both halves)

    // ---------------- hypernetwork prologue (per-sample, tiny) ----------------
    float cv[8];
#pragma unroll
    for (int k = 0; k < 8; ++k) cv[k] = c[b * 8 + k];

    float w1[8];
#pragma unroll
    for (int m = 0; m < 8; ++m) {
        float a = mlp_b1[m];
#pragma unroll
        for (int k = 0; k < 8; ++k) a = fmaf(cv[k], mlp_w1[m * 8 + k], a);
        w1[m] = lrelu(a);
    }
    float w2[8];
#pragma unroll
    for (int m = 0; m < 8; ++m) {
        float a = mlp_b2[m];
#pragma unroll
        for (int k = 0; k < 8; ++k) a = fmaf(w1[k], mlp_w2[m * 8 + k], a);
        w2[m] = lrelu(a);
    }

    auto proj8 = [&](const float* __restrict__ wrow, float bias) -> float {
        float a = bias;
#pragma unroll
        for (int k = 0; k < 8; ++k) a = fmaf(w2[k], wrow[k], a);
        return a;
    };

    // recurrent weights this lane needs: w_hh[r][j], w_hh[r][16+j], w_hh[r][32+j]
    float whr[16], whi[16], whn[16];
#pragma unroll
    for (int k = 0; k < 16; ++k) {
        whr[k] = proj8(phh_w + (size_t)(k * 48 + j) * 8,      phh_b[k * 48 + j]);
        whi[k] = proj8(phh_w + (size_t)(k * 48 + 16 + j) * 8, phh_b[k * 48 + 16 + j]);
        whn[k] = proj8(phh_w + (size_t)(k * 48 + 32 + j) * 8, phh_b[k * 48 + 32 + j]);
    }
    const float wih_r = proj8(pih_w + (size_t)j * 8,        pih_b[j]);
    const float wih_i = proj8(pih_w + (size_t)(16 + j) * 8, pih_b[16 + j]);
    const float wih_n = proj8(pih_w + (size_t)(32 + j) * 8, pih_b[32 + j]);

    const float bih_r = proj8(pbih_w + (size_t)j * 8,        pbih_b[j]);
    const float bih_i = proj8(pbih_w + (size_t)(16 + j) * 8, pbih_b[16 + j]);
    const float bih_n = proj8(pbih_w + (size_t)(32 + j) * 8, pbih_b[32 + j]);
    const float bhh_r = proj8(pbhh_w + (size_t)j * 8,        pbhh_b[j]);
    const float bhh_i = proj8(pbhh_w + (size_t)(16 + j) * 8, pbhh_b[16 + j]);
    const float bhh_n = proj8(pbhh_w + (size_t)(32 + j) * 8, pbhh_b[32 + j]);

    const float cbr = bih_r + bhh_r;   // biases for reset gate fuse
    const float cbi = bih_i + bhh_i;   // biases for input gate fuse
    // bih_n / bhh_n stay separate: newgate = tanh(i_n + reset * (acc_n + bhh_n))

    float ow[16];
#pragma unroll
    for (int k = 0; k < 16; ++k) ow[k] = out_w[k];
    const float ob = out_b[0];

    // ---------------- recurrence ----------------
    float h = h0[b * R + j];
    const float* __restrict__ xp = x + (size_t)b * T;
    float* __restrict__ yp = out + (size_t)b * T;

    float xcur = xp[lane];   // 32 timesteps staged per lane
    for (int t0 = 0; t0 < T; t0 += 32) {
        float xnext = (t0 + 32 < T) ? xp[t0 + 32 + lane] : 0.f;  // prefetch next chunk
        for (int tb = 0; tb < 32; tb += 8) {                      // keep SASS body small (I$)
#pragma unroll
            for (int tt = 0; tt < 8; ++tt) {
                const int ti = tb + tt;
                const float xt = __shfl_sync(FULLMASK, xcur, ti, 32);

                // broadcast current hidden state (h entering this step = hs[t-1])
                float hr[16];
#pragma unroll
                for (int k = 0; k < 16; ++k) hr[k] = __shfl_sync(FULLMASK, h, k, 16);

                float sr0 = 0.f, sr1 = 0.f, si0 = 0.f, si1 = 0.f, sn0 = 0.f, sn1 = 0.f;
#pragma unroll
                for (int k = 0; k < 8; ++k) {
                    sr0 = fmaf(hr[k], whr[k], sr0);     sr1 = fmaf(hr[k + 8], whr[k + 8], sr1);
                    si0 = fmaf(hr[k], whi[k], si0);     si1 = fmaf(hr[k + 8], whi[k + 8], si1);
                    sn0 = fmaf(hr[k], whn[k], sn0);     sn1 = fmaf(hr[k + 8], whn[k + 8], sn1);
                }

                const float rg = sigm((sr0 + sr1) + fmaf(xt, wih_r, cbr));
                const float ig = sigm((si0 + si1) + fmaf(xt, wih_i, cbi));
                const float hn = (sn0 + sn1) + bhh_n;
                const float ng = tanh_acc(fmaf(rg, hn, fmaf(xt, wih_n, bih_n)));

                // y for the PREVIOUS timestep from this step's broadcast (off critical path)
                float y0 = ob, y1 = 0.f;
#pragma unroll
                for (int k = 0; k < 8; ++k) {
                    y0 = fmaf(hr[k], ow[k], y0);
                    y1 = fmaf(hr[k + 8], ow[k + 8], y1);
                }
                const int tg = t0 + ti;
                if (lane == 0 && tg > 0) yp[tg - 1] = y0 + y1;

                h = fmaf(ig, h - ng, ng);   // hy = ng + ig*(h - ng)
            }
        }
        xcur = xnext;
    }

    // final y[T-1] and h_last
    float yf = ob;
#pragma unroll
    for (int k = 0; k < 16; ++k)
        yf = fmaf(__shfl_sync(FULLMASK, h, k, 16), ow[k], yf);
    if (lane == 0) yp[T - 1] = yf;
    if (lane < 16) out[(size_t)B * T + b * R + lane] = h;
}

extern "C" void kernel_launch(void* const* d_in, const int* in_sizes, int n_in,
                              void* d_out, int out_size) {
    (void)in_sizes; (void)n_in; (void)out_size;
    hypergru_kernel<<<B, 32>>>(
        (const float*)d_in[0],  (const float*)d_in[1],  (const float*)d_in[2],
        (const float*)d_in[3],  (const float*)d_in[4],  (const float*)d_in[5],
        (const float*)d_in[6],  (const float*)d_in[7],  (const float*)d_in[8],
        (const float*)d_in[9],  (const float*)d_in[10], (const float*)d_in[11],
        (const float*)d_in[12], (const float*)d_in[13], (const float*)d_in[14],
        (const float*)d_in[15], (const float*)d_in[16],
        (float*)d_out);
}

// round 2
// speedup vs baseline: 1.6125x; 1.6125x over previous
#include <cuda_runtime.h>
#include <cuda_bf16.h>

#define FULLMASK 0xffffffffu

namespace {
constexpr int B = 64;
constexpr int T = 32768;
constexpr int R = 16;
}

// Scratch: hidden states for all steps (y-projection done in a second pass).
__device__ float g_hs[(size_t)B * T * R];   // 128 MiB

__device__ __forceinline__ float lrelu(float v) { return v >= 0.f ? v : 0.1f * v; }
__device__ __forceinline__ float tanh_fast(float v) {
    float r;
    asm("tanh.approx.f32 %0, %1;" : "=f"(r) : "f"(v));
    return r;
}

__global__ void __launch_bounds__(32, 1) hypergru_rnn_kernel(
    const float* __restrict__ x,      // [B,1,T]
    const float* __restrict__ c,      // [B,8]
    const float* __restrict__ h0,     // [1,B,R]
    const float* __restrict__ mlp_w1, const float* __restrict__ mlp_b1,
    const float* __restrict__ mlp_w2, const float* __restrict__ mlp_b2,
    const float* __restrict__ pih_w,  const float* __restrict__ pih_b,
    const float* __restrict__ phh_w,  const float* __restrict__ phh_b,
    const float* __restrict__ pbih_w, const float* __restrict__ pbih_b,
    const float* __restrict__ pbhh_w, const float* __restrict__ pbhh_b,
    float* __restrict__ out)          // only h_last region written here
{
    const int b    = blockIdx.x;
    const int lane = threadIdx.x;
    const int j    = lane & 15;          // hidden unit owned by this lane
    const int koff = (lane >> 4) * 8;    // lower half sums k=0..7, upper k=8..15

    // ---------------- hypernetwork prologue ----------------
    float cv[8];
#pragma unroll
    for (int k = 0; k < 8; ++k) cv[k] = c[b * 8 + k];

    float w1[8];
#pragma unroll
    for (int m = 0; m < 8; ++m) {
        float a = mlp_b1[m];
#pragma unroll
        for (int k = 0; k < 8; ++k) a = fmaf(cv[k], mlp_w1[m * 8 + k], a);
        w1[m] = lrelu(a);
    }
    float w2[8];
#pragma unroll
    for (int m = 0; m < 8; ++m) {
        float a = mlp_b2[m];
#pragma unroll
        for (int k = 0; k < 8; ++k) a = fmaf(w1[k], mlp_w2[m * 8 + k], a);
        w2[m] = lrelu(a);
    }

    auto proj8 = [&](const float* __restrict__ wrow, float bias) -> float {
        float a = bias;
#pragma unroll
        for (int k = 0; k < 8; ++k) a = fmaf(w2[k], wrow[k], a);
        return a;
    };

    // Recurrent weights this lane needs: only its 8 k-terms of each gate.
    // r/i-gate weights are pre-halved (sigmoid computed as 0.5*tanh(v/2)+0.5).
    float whr_h[8], whi_h[8], whn[8];
#pragma unroll
    for (int k = 0; k < 8; ++k) {
        const int kk = k + koff;
        whr_h[k] = 0.5f * proj8(phh_w + (size_t)(kk * 48 + j) * 8,      phh_b[kk * 48 + j]);
        whi_h[k] = 0.5f * proj8(phh_w + (size_t)(kk * 48 + 16 + j) * 8, phh_b[kk * 48 + 16 + j]);
        whn[k]   =        proj8(phh_w + (size_t)(kk * 48 + 32 + j) * 8, phh_b[kk * 48 + 32 + j]);
    }
    const float wih_r_h = 0.5f * proj8(pih_w + (size_t)j * 8,        pih_b[j]);
    const float wih_i_h = 0.5f * proj8(pih_w + (size_t)(16 + j) * 8, pih_b[16 + j]);
    const float wih_n   =        proj8(pih_w + (size_t)(32 + j) * 8, pih_b[32 + j]);

    const float bih_r = proj8(pbih_w + (size_t)j * 8,        pbih_b[j]);
    const float bih_i = proj8(pbih_w + (size_t)(16 + j) * 8, pbih_b[16 + j]);
    const float bih_n = proj8(pbih_w + (size_t)(32 + j) * 8, pbih_b[32 + j]);
    const float bhh_r = proj8(pbhh_w + (size_t)j * 8,        pbhh_b[j]);
    const float bhh_i = proj8(pbhh_w + (size_t)(16 + j) * 8, pbhh_b[16 + j]);
    const float bhh_n = proj8(pbhh_w + (size_t)(32 + j) * 8, pbhh_b[32 + j]);

    const float cbr_h = 0.5f * (bih_r + bhh_r);
    const float cbi_h = 0.5f * (bih_i + bhh_i);

    // ---------------- recurrence ----------------
    float h = h0[b * R + j];
    const float* __restrict__ xp = x + (size_t)b * T;
    float* __restrict__ hsp = g_hs + (size_t)b * T * R;

    float xcur = xp[lane];   // 32 timesteps staged per lane
    for (int t0 = 0; t0 < T; t0 += 32) {
        float xnext = (t0 + 32 < T) ? xp[t0 + 32 + lane] : 0.f;  // prefetch
        for (int tb = 0; tb < 32; tb += 8) {                      // small SASS body (I$)
#pragma unroll
            for (int tt = 0; tt < 8; ++tt) {
                const int ti = tb + tt;
                const float xt = __shfl_sync(FULLMASK, xcur, ti, 32);

                // each half fetches only the 8 h-values it needs
                float hrv[8];
#pragma unroll
                for (int k = 0; k < 8; ++k)
                    hrv[k] = __shfl_sync(FULLMASK, h, k + koff, 16);

                float sr0 = 0.f, sr1 = 0.f, si0 = 0.f, si1 = 0.f, sn0 = 0.f, sn1 = 0.f;
#pragma unroll
                for (int k = 0; k < 4; ++k) {
                    sr0 = fmaf(hrv[k], whr_h[k], sr0);  sr1 = fmaf(hrv[k + 4], whr_h[k + 4], sr1);
                    si0 = fmaf(hrv[k], whi_h[k], si0);  si1 = fmaf(hrv[k + 4], whi_h[k + 4], si1);
                    sn0 = fmaf(hrv[k], whn[k],   sn0);  sn1 = fmaf(hrv[k + 4], whn[k + 4],   sn1);
                }
                const float srp = sr0 + sr1;
                const float sip = si0 + si1;
                const float snp = sn0 + sn1;
                // combine the two k-halves
                const float srf = srp + __shfl_xor_sync(FULLMASK, srp, 16);
                const float sif = sip + __shfl_xor_sync(FULLMASK, sip, 16);
                const float snf = snp + __shfl_xor_sync(FULLMASK, snp, 16);

                const float i_r = fmaf(xt, wih_r_h, cbr_h);
                const float i_i = fmaf(xt, wih_i_h, cbi_h);
                const float i_n = fmaf(xt, wih_n, bih_n);

                const float rg = fmaf(tanh_fast(srf + i_r), 0.5f, 0.5f);
                const float ig = fmaf(tanh_fast(sif + i_i), 0.5f, 0.5f);
                const float hn = snf + bhh_n;
                const float ng = tanh_fast(fmaf(rg, hn, i_n));

                h = fmaf(ig, h - ng, ng);   // hy = ng + ig*(h - ng)

                if (lane < 16) hsp[(size_t)(t0 + ti) * R + lane] = h;
            }
        }
        xcur = xnext;
    }

    if (lane < 16) out[(size_t)B * T + b * R + lane] = h;
}

// Second pass: y[b,t] = dot(hs[b,t,:], out_w) + out_b  (bandwidth-bound, parallel)
__global__ void __launch_bounds__(256) out_proj_kernel(
    const float* __restrict__ out_w, const float* __restrict__ out_b,
    float* __restrict__ out)
{
    const int idx = blockIdx.x * 256 + threadIdx.x;   // idx = b*T + t  (covers B*T exactly)
    const float4* __restrict__ hp = reinterpret_cast<const float4*>(g_hs) + (size_t)idx * 4;
    float4 v0 = hp[0], v1 = hp[1], v2 = hp[2], v3 = hp[3];
    const float4* __restrict__ wp = reinterpret_cast<const float4*>(out_w);
    float4 w0 = __ldg(wp), w1 = __ldg(wp + 1), w2 = __ldg(wp + 2), w3 = __ldg(wp + 3);

    float a = __ldg(out_b);
    a = fmaf(v0.x, w0.x, a); a = fmaf(v0.y, w0.y, a); a = fmaf(v0.z, w0.z, a); a = fmaf(v0.w, w0.w, a);
    a = fmaf(v1.x, w1.x, a); a = fmaf(v1.y, w1.y, a); a = fmaf(v1.z, w1.z, a); a = fmaf(v1.w, w1.w, a);
    a = fmaf(v2.x, w2.x, a); a = fmaf(v2.y, w2.y, a); a = fmaf(v2.z, w2.z, a); a = fmaf(v2.w, w2.w, a);
    a = fmaf(v3.x, w3.x, a); a = fmaf(v3.y, w3.y, a); a = fmaf(v3.z, w3.z, a); a = fmaf(v3.w, w3.w, a);
    out[idx] = a;
}

extern "C" void kernel_launch(void* const* d_in, const int* in_sizes, int n_in,
                              void* d_out, int out_size) {
    (void)in_sizes; (void)n_in; (void)out_size;
    hypergru_rnn_kernel<<<B, 32>>>(
        (const float*)d_in[0],  (const float*)d_in[1],  (const float*)d_in[2],
        (const float*)d_in[3],  (const float*)d_in[4],  (const float*)d_in[5],
        (const float*)d_in[6],  (const float*)d_in[7],  (const float*)d_in[8],
        (const float*)d_in[9],  (const float*)d_in[10], (const float*)d_in[11],
        (const float*)d_in[12], (const float*)d_in[13], (const float*)d_in[14],
        (float*)d_out);
    out_proj_kernel<<<(B * T) / 256, 256>>>(
        (const float*)d_in[15], (const float*)d_in[16], (float*)d_out);
}